// round 14
// baseline (speedup 1.0000x reference)
#include <cuda_runtime.h>
#include <cuda_fp16.h>
#include <cstdint>

#define B_ 64
#define C_ 64
#define T_ 4000
#define TS_ 10           // t-splits for gram
#define TSPAN 400        // t per split
#define NSTG 7           // stages of 64 t (6 full + 16-t remainder)
#define TC_C 160         // t-chunk width for apply kernel
#define NCH_C 25
#define CHPC 2           // chunks per apply CTA
#define NCKB 13          // ceil(25/2) apply CTAs along t

// Scratch (static device globals — allocation-free)
__device__ float g_gp[B_ * TS_ * C_ * C_];   // partial Grams (10.5 MB)
__device__ float g_sxp[B_ * TS_ * C_];       // partial channel sums
__device__ uint16_t g_ath[B_ * 4096];        // gamma*M^T, fp16, swizzled (8KB/batch)
__device__ unsigned int g_cnt[B_];           // last-arriver tickets (self-resetting)

extern __shared__ float smem_dyn[];

__device__ __forceinline__ uint32_t smem_u32(const void* p) {
    uint32_t a;
    asm("{ .reg .u64 t; cvta.to.shared.u64 t, %1; cvt.u32.u64 %0, t; }" : "=r"(a) : "l"(p));
    return a;
}

#define LDSM4(r, addr)                                                       \
    asm volatile("ldmatrix.sync.aligned.m8n8.x4.shared.b16 {%0,%1,%2,%3}, [%4];" \
        : "=r"((r)[0]), "=r"((r)[1]), "=r"((r)[2]), "=r"((r)[3]) : "r"(addr))

#define LDSM4T(r, addr)                                                      \
    asm volatile("ldmatrix.sync.aligned.m8n8.x4.trans.shared.b16 {%0,%1,%2,%3}, [%4];" \
        : "=r"((r)[0]), "=r"((r)[1]), "=r"((r)[2]), "=r"((r)[3]) : "r"(addr))

#define MMAF16(c, a, b0v, b1v)                                               \
    asm volatile("mma.sync.aligned.m16n8k16.row.col.f32.f16.f16.f32 "        \
        "{%0,%1,%2,%3}, {%4,%5,%6,%7}, {%8,%9}, {%0,%1,%2,%3};"              \
        : "+f"((c)[0]), "+f"((c)[1]), "+f"((c)[2]), "+f"((c)[3])             \
        : "r"((a)[0]), "r"((a)[1]), "r"((a)[2]), "r"((a)[3]),                \
          "r"(b0v), "r"(b1v))

#define CP16(dst, src, sz)                                                   \
    asm volatile("cp.async.cg.shared.global [%0], [%1], 16, %2;"             \
        :: "r"(dst), "l"(src), "r"(sz) : "memory")
#define CP16F(dst, src)                                                      \
    asm volatile("cp.async.cg.shared.global [%0], [%1], 16;"                 \
        :: "r"(dst), "l"(src) : "memory")
#define CP_COMMIT()  asm volatile("cp.async.commit_group;" ::: "memory")
#define CP_WAIT(n)   asm volatile("cp.async.wait_group %0;" :: "n"(n) : "memory")

__device__ __forceinline__ uint2 cvt_h4(float4 v) {
    __half2 p0 = __floats2half2_rn(v.x, v.y);
    __half2 p1 = __floats2half2_rn(v.z, v.w);
    uint2 r;
    r.x = *(uint32_t*)&p0;
    r.y = *(uint32_t*)&p1;
    return r;
}

// ---------------------------------------------------------------------------
// Kernel A (HMMA fp16 + cp.async): partial Gram over a 400-t split,
// with attn FUSED via atomic last-arriver per batch.
// ---------------------------------------------------------------------------
__global__ void __launch_bounds__(256, 4) k_gram_mma(const float* __restrict__ x,
                                                     const float* __restrict__ w1,
                                                     const float* __restrict__ b1,
                                                     const float* __restrict__ w2,
                                                     const float* __restrict__ b2,
                                                     const float* __restrict__ gptr) {
    char* ring = (char*)smem_dyn;                 // 2 x [64 rows x 272B] = 34816 B
    uint16_t* hbuf = (uint16_t*)(ring + 34816);   // 2 x 8KB fp16 swizzled
    __shared__ float red[256];
    __shared__ unsigned int ticket;

    const int split = blockIdx.x, b = blockIdx.y;
    const int tid = threadIdx.x, lane = tid & 31, wid = tid >> 5;
    const int mg = wid >> 1, ng = wid & 1;
    const uint32_t hbase = smem_u32(hbuf);

    const int srow = tid >> 2, sq = tid & 3;
    const float* xsrc = x + ((size_t)b * C_ + srow) * T_ + split * TSPAN + sq * 16;
    const uint32_t rmy = smem_u32(ring) + srow * 272 + sq * 64;
    char* rmyp = ring + srow * 272 + sq * 64;

    const int arow = 16 * mg + (lane & 7) + 8 * ((lane >> 3) & 1);
    const int achk = lane >> 4;
    const int brow0 = 32 * ng + 8 * (lane >> 4) + (lane & 7);
    const int brow1 = brow0 + 16;
    const int bchk = (lane >> 3) & 1;

    float D[4][4];
#pragma unroll
    for (int j = 0; j < 4; ++j)
#pragma unroll
        for (int i = 0; i < 4; ++i) D[j][i] = 0.f;
    float sx = 0.f;

#define G_ISSUE(s) do {                                                      \
    const uint32_t _d = rmy + ((s) & 1) * 17408;                             \
    const int _sz = ((s) < NSTG - 1 || sq == 0) ? 16 : 0;                    \
    const float* _sp = _sz ? (xsrc + (s) * 64) : xsrc;                       \
    CP16(_d,      _sp,      _sz);                                            \
    CP16(_d + 16, _sp + 4,  _sz);                                            \
    CP16(_d + 32, _sp + 8,  _sz);                                            \
    CP16(_d + 48, _sp + 12, _sz);                                            \
    CP_COMMIT();                                                             \
} while (0)

    G_ISSUE(0);

#pragma unroll 1
    for (int s = 0; s < NSTG; ++s) {
        CP_WAIT(0);
        if (s + 1 < NSTG) G_ISSUE(s + 1);   // early issue (own-slot safe)
        char* rp = rmyp + (s & 1) * 17408;
        uint16_t* hb = hbuf + (s & 1) * 4096;
#pragma unroll
        for (int i = 0; i < 4; ++i) {
            float4 v = *(const float4*)(rp + 16 * i);
            sx += v.x + v.y + v.z + v.w;
            uint2 hp = cvt_h4(v);
            const int col = sq * 16 + 4 * i;
            const int ad = srow * 128 + ((((col >> 3) ^ (srow & 7))) << 4) + ((col & 7) << 1);
            *(uint2*)((char*)hb + ad) = hp;
        }
        __syncthreads();

        const uint32_t sbb = hbase + (s & 1) * 8192;
#pragma unroll
        for (int k = 0; k < 4; ++k) {
            const int c0 = k * 2;
            uint32_t a[4], bh[8];
            LDSM4(a, sbb + arow * 128 + (((c0 + achk) ^ (arow & 7)) << 4));
            LDSM4(bh + 0, sbb + brow0 * 128 + (((c0 + bchk) ^ (brow0 & 7)) << 4));
            LDSM4(bh + 4, sbb + brow1 * 128 + (((c0 + bchk) ^ (brow1 & 7)) << 4));
#pragma unroll
            for (int j = 0; j < 4; ++j)
                MMAF16(D[j], a, bh[2 * j], bh[2 * j + 1]);
        }
    }

    // channel sums (4 threads per channel)
    red[tid] = sx;
    __syncthreads();
    if (tid < 64)
        g_sxp[(b * TS_ + split) * C_ + tid] =
            red[4 * tid] + red[4 * tid + 1] + red[4 * tid + 2] + red[4 * tid + 3];

    // write D tile
    float* gp = g_gp + (size_t)(b * TS_ + split) * (C_ * C_);
    const int crow = 16 * mg + (lane >> 2);
    const int ccol0 = 32 * ng + 2 * (lane & 3);
#pragma unroll
    for (int j = 0; j < 4; ++j) {
        const int c = ccol0 + 8 * j;
        *(float2*)(gp + crow * C_ + c)       = make_float2(D[j][0], D[j][1]);
        *(float2*)(gp + (crow + 8) * C_ + c) = make_float2(D[j][2], D[j][3]);
    }

    // ---- fused attn: last CTA per batch does softmax ----
    __threadfence();                 // release own gp/sxp stores
    __syncthreads();                 // all threads fenced
    if (tid == 0) ticket = atomicAdd(&g_cnt[b], 1u);
    __syncthreads();

    if (ticket == TS_ - 1) {
        __threadfence();             // acquire other CTAs' gp/sxp
        float* Es  = (float*)smem_dyn;        // [64][65]
        float* sxs = Es + 64 * 65;            // [64]

        float S11 = 0.f, S21 = 0.f;
#pragma unroll
        for (int j = 0; j < 8; ++j) { S11 += w1[j] * w2[j]; S21 += b1[j] * w2[j]; }
        const float ga = *gptr;

        if (tid < 64) {
            float s = 0.f;
#pragma unroll
            for (int p = 0; p < TS_; ++p) s += g_sxp[(b * TS_ + p) * C_ + tid];
            sxs[tid] = s;
        }
        __syncthreads();

        const float* gpb = g_gp + (size_t)b * TS_ * (C_ * C_);
        for (int i = tid; i < C_ * C_; i += 256) {
            float g = 0.f;
#pragma unroll
            for (int p = 0; p < TS_; ++p) g += gpb[p * (C_ * C_) + i];
            const int e = i & 63;
            Es[(i >> 6) * 65 + e] = S11 * g + S21 * sxs[e];
        }
        __syncthreads();

        char* ath = (char*)g_ath + (size_t)b * 8192;
        for (int r = wid; r < C_; r += 8) {
            float v0 = Es[r * 65 + lane], v1 = Es[r * 65 + lane + 32];
            float mx = fmaxf(v0, v1), mn = fminf(v0, v1);
#pragma unroll
            for (int o = 16; o; o >>= 1) {
                mx = fmaxf(mx, __shfl_xor_sync(0xffffffffu, mx, o));
                mn = fminf(mn, __shfl_xor_sync(0xffffffffu, mn, o));
            }
            const float inv = 1.f / (mx - mn + 1e-8f);
            const float nmax = (mx - mn) * inv;
            float e0 = expf((v0 - mn) * inv - nmax);
            float e1 = expf((v1 - mn) * inv - nmax);
            float s = e0 + e1;
#pragma unroll
            for (int o = 16; o; o >>= 1) s += __shfl_xor_sync(0xffffffffu, s, o);
            const float invs = ga / s;   // fold gamma into M
            const __half h0 = __float2half_rn(e0 * invs);
            const __half h1 = __float2half_rn(e1 * invs);
            const int c0 = lane, c1 = lane + 32;
            *(uint16_t*)(ath + c0 * 128 + (((r >> 3) ^ (c0 & 7)) << 4) + ((r & 7) << 1)) =
                *(const uint16_t*)&h0;
            *(uint16_t*)(ath + c1 * 128 + (((r >> 3) ^ (c1 & 7)) << 4) + ((r & 7) << 1)) =
                *(const uint16_t*)&h1;
        }
        __syncthreads();
        if (tid == 0) g_cnt[b] = 0;      // reset for next graph replay
    }
}

// ---------------------------------------------------------------------------
// Kernel C (R10 proven version): out = x + (gamma*M)^T X.
// Grid (NCKB, B_) = (13,64), CHPC=2, 40KB fp32 stage, 73.7KB smem.
// ---------------------------------------------------------------------------
__global__ void __launch_bounds__(256, 3) k_apply_mma(const float* __restrict__ x,
                                                      float* __restrict__ out) {
    uint16_t* At = (uint16_t*)smem_dyn;     // 8 KB fp16 swizzled (gamma*M^T)
    uint16_t* Xs = At + 4096;               // 24 KB fp16 [64][192] swizzled
    float*    Xf = (float*)(Xs + 64 * 192); // 40 KB fp32 linear stage (2560 f4)

    const int b = blockIdx.y, ckb = blockIdx.x;
    const int tid = threadIdx.x, lane = tid & 31, wid = tid >> 5;
    const int mg = wid >> 1, ngw = wid & 1;

    // stage At once: raw vector copy (pre-swizzled + gamma-folded)
    {
        const float4* src = (const float4*)((const char*)g_ath + (size_t)b * 8192);
        float4* dst = (float4*)At;
        dst[tid] = src[tid];
        dst[tid + 256] = src[tid + 256];
    }

    const float* xb = x + (size_t)b * C_ * T_;
    const uint32_t xfb = smem_u32(Xf);

#define A_ISSUE(ck) do {                                                     \
    const int _t0 = (ck) * TC_C;                                             \
    _Pragma("unroll")                                                        \
    for (int k = 0; k < 10; ++k) {                                           \
        const int v = tid + k * 256;                                         \
        const int row = v / 40, q = v % 40;                                  \
        CP16F(xfb + v * 16, xb + (size_t)row * T_ + _t0 + 4 * q);            \
    }                                                                        \
    CP_COMMIT();                                                             \
} while (0)

    const int c0 = ckb * CHPC;
    if (c0 < NCH_C) A_ISSUE(c0);

    const int arow = 16 * mg + (lane & 7) + 8 * ((lane >> 3) & 1);
    const int achk = lane >> 4;
    const int bkoff = 8 * ((lane >> 3) & 1) + (lane & 7);
    const int bjj = lane >> 4;
    const int orow = 16 * mg + (lane >> 2);

#pragma unroll 1
    for (int j = 0; j < CHPC; ++j) {
        const int ck = c0 + j;
        if (ck >= NCH_C) break;
        const int t0 = ck * TC_C;

        CP_WAIT(0);                       // chunk ck's fp32 data landed
#pragma unroll
        for (int k = 0; k < 10; ++k) {
            const int v = tid + k * 256;
            const int row = v / 40, q = v % 40;
            float4 w = *(const float4*)(Xf + v * 4);
            uint2 hp = cvt_h4(w);
            const int col = 4 * q;
            const int ad = row * 384 + ((((col >> 3) ^ (row & 7))) << 4) + ((col & 7) << 1);
            *(uint2*)((char*)Xs + ad) = hp;
        }
        if (j + 1 < CHPC && ck + 1 < NCH_C) A_ISSUE(ck + 1);
        __syncthreads();

        float acc[10][4];
#pragma unroll
        for (int jj = 0; jj < 10; ++jj)
#pragma unroll
            for (int i = 0; i < 4; ++i) acc[jj][i] = 0.f;

#pragma unroll
        for (int kk = 0; kk < 4; ++kk) {
            uint32_t ah[4];
            LDSM4(ah, smem_u32(At) + arow * 128 + (((kk * 2 + achk) ^ (arow & 7)) << 4));
            const int krow = kk * 16 + bkoff;
#pragma unroll
            for (int p = 0; p < 5; ++p) {
                const int nchunk = ngw * 10 + 2 * p + bjj;
                uint32_t bh[4];
                LDSM4T(bh, smem_u32(Xs) + krow * 384 + ((nchunk ^ (krow & 7)) << 4));
                MMAF16(acc[2 * p],     ah, bh[0], bh[1]);
                MMAF16(acc[2 * p + 1], ah, bh[2], bh[3]);
            }
        }

        // epilogue: out = x_fp16(smem) + acc
        float* ob = out + (size_t)b * C_ * T_ + t0;
#pragma unroll
        for (int jj = 0; jj < 10; ++jj) {
            const int tc = ngw * 80 + 8 * jj + 2 * (lane & 3);
            const int ad0 = orow * 384 + (((tc >> 3) ^ (orow & 7)) << 4) + ((tc & 7) << 1);
            const int ad1 = (orow + 8) * 384 + (((tc >> 3) ^ ((orow + 8) & 7)) << 4) + ((tc & 7) << 1);
            __half2 xh0 = *(const __half2*)((const char*)Xs + ad0);
            __half2 xh1 = *(const __half2*)((const char*)Xs + ad1);
            float2 x0 = __half22float2(xh0);
            float2 x1 = __half22float2(xh1);
            float2 o0 = make_float2(acc[jj][0] + x0.x, acc[jj][1] + x0.y);
            float2 o1 = make_float2(acc[jj][2] + x1.x, acc[jj][3] + x1.y);
            *(float2*)(ob + (size_t)orow * T_ + tc) = o0;
            *(float2*)(ob + (size_t)(orow + 8) * T_ + tc) = o1;
        }
        __syncthreads();                  // Xs reads done before next convert
    }
}

// ---------------------------------------------------------------------------
extern "C" void kernel_launch(void* const* d_in, const int* in_sizes, int n_in,
                              void* d_out, int out_size) {
    const float* x  = (const float*)d_in[0];
    const float* w1 = (const float*)d_in[1];
    const float* b1 = (const float*)d_in[2];
    const float* w2 = (const float*)d_in[3];
    const float* b2 = (const float*)d_in[4];
    const float* gm = (const float*)d_in[5];
    float* out = (float*)d_out;

    const int smem_gram  = 34816 + 2 * 8192;            // 51,200 B -> 4 CTAs/SM
    const int smem_apply = 8192 + 24576 + 40960;        // 73,728 B -> 3 CTAs/SM
    cudaFuncSetAttribute(k_gram_mma,  cudaFuncAttributeMaxDynamicSharedMemorySize, smem_gram);
    cudaFuncSetAttribute(k_apply_mma, cudaFuncAttributeMaxDynamicSharedMemorySize, smem_apply);

    k_gram_mma<<<dim3(TS_, B_), 256, smem_gram>>>(x, w1, b1, w2, b2, gm);
    k_apply_mma<<<dim3(NCKB, B_), 256, smem_apply>>>(x, out);
}

// round 15
// speedup vs baseline: 1.0790x; 1.0790x over previous
#include <cuda_runtime.h>
#include <cuda_fp16.h>
#include <cstdint>

#define B_ 64
#define C_ 64
#define T_ 4000
#define TS_ 10           // t-splits for gram
#define TSPAN 400        // t per split
#define NSTG 7           // stages of 64 t (6 full + 16-t remainder)
#define TC_C 160         // t-chunk width for apply kernel
#define NCH_C 25
#define CHPC 2           // chunks per apply CTA
#define NCKB 13          // ceil(25/2) apply CTAs along t

// Scratch (static device globals — allocation-free)
__device__ float g_gp[B_ * TS_ * C_ * C_];   // partial Grams (10.5 MB)
__device__ float g_sxp[B_ * TS_ * C_];       // partial channel sums
__device__ uint16_t g_ath[B_ * 4096];        // gamma*M^T, fp16, swizzled (8KB/batch)

extern __shared__ float smem_dyn[];

__device__ __forceinline__ uint32_t smem_u32(const void* p) {
    uint32_t a;
    asm("{ .reg .u64 t; cvta.to.shared.u64 t, %1; cvt.u32.u64 %0, t; }" : "=r"(a) : "l"(p));
    return a;
}

#define LDSM4(r, addr)                                                       \
    asm volatile("ldmatrix.sync.aligned.m8n8.x4.shared.b16 {%0,%1,%2,%3}, [%4];" \
        : "=r"((r)[0]), "=r"((r)[1]), "=r"((r)[2]), "=r"((r)[3]) : "r"(addr))

#define LDSM4T(r, addr)                                                      \
    asm volatile("ldmatrix.sync.aligned.m8n8.x4.trans.shared.b16 {%0,%1,%2,%3}, [%4];" \
        : "=r"((r)[0]), "=r"((r)[1]), "=r"((r)[2]), "=r"((r)[3]) : "r"(addr))

#define MMAF16(c, a, b0v, b1v)                                               \
    asm volatile("mma.sync.aligned.m16n8k16.row.col.f32.f16.f16.f32 "        \
        "{%0,%1,%2,%3}, {%4,%5,%6,%7}, {%8,%9}, {%0,%1,%2,%3};"              \
        : "+f"((c)[0]), "+f"((c)[1]), "+f"((c)[2]), "+f"((c)[3])             \
        : "r"((a)[0]), "r"((a)[1]), "r"((a)[2]), "r"((a)[3]),                \
          "r"(b0v), "r"(b1v))

#define CP16(dst, src, sz)                                                   \
    asm volatile("cp.async.cg.shared.global [%0], [%1], 16, %2;"             \
        :: "r"(dst), "l"(src), "r"(sz) : "memory")
#define CP16F(dst, src)                                                      \
    asm volatile("cp.async.cg.shared.global [%0], [%1], 16;"                 \
        :: "r"(dst), "l"(src) : "memory")
#define CP_COMMIT()  asm volatile("cp.async.commit_group;" ::: "memory")
#define CP_WAIT(n)   asm volatile("cp.async.wait_group %0;" :: "n"(n) : "memory")

__device__ __forceinline__ uint2 cvt_h4(float4 v) {
    __half2 p0 = __floats2half2_rn(v.x, v.y);
    __half2 p1 = __floats2half2_rn(v.z, v.w);
    uint2 r;
    r.x = *(uint32_t*)&p0;
    r.y = *(uint32_t*)&p1;
    return r;
}

// ---------------------------------------------------------------------------
// Kernel A (R10 proven): partial Gram over a 400-t split.
// ---------------------------------------------------------------------------
__global__ void __launch_bounds__(256, 4) k_gram_mma(const float* __restrict__ x) {
    char* ring = (char*)smem_dyn;                 // 2 x [64 rows x 272B] = 34816 B
    uint16_t* hbuf = (uint16_t*)(ring + 34816);   // 2 x 8KB fp16 swizzled
    __shared__ float red[256];

    const int split = blockIdx.x, b = blockIdx.y;
    const int tid = threadIdx.x, lane = tid & 31, wid = tid >> 5;
    const int mg = wid >> 1, ng = wid & 1;
    const uint32_t hbase = smem_u32(hbuf);

    const int srow = tid >> 2, sq = tid & 3;
    const float* xsrc = x + ((size_t)b * C_ + srow) * T_ + split * TSPAN + sq * 16;
    const uint32_t rmy = smem_u32(ring) + srow * 272 + sq * 64;
    char* rmyp = ring + srow * 272 + sq * 64;

    const int arow = 16 * mg + (lane & 7) + 8 * ((lane >> 3) & 1);
    const int achk = lane >> 4;
    const int brow0 = 32 * ng + 8 * (lane >> 4) + (lane & 7);
    const int brow1 = brow0 + 16;
    const int bchk = (lane >> 3) & 1;

    float D[4][4];
#pragma unroll
    for (int j = 0; j < 4; ++j)
#pragma unroll
        for (int i = 0; i < 4; ++i) D[j][i] = 0.f;
    float sx = 0.f;

#define G_ISSUE(s) do {                                                      \
    const uint32_t _d = rmy + ((s) & 1) * 17408;                             \
    const int _sz = ((s) < NSTG - 1 || sq == 0) ? 16 : 0;                    \
    const float* _sp = _sz ? (xsrc + (s) * 64) : xsrc;                       \
    CP16(_d,      _sp,      _sz);                                            \
    CP16(_d + 16, _sp + 4,  _sz);                                            \
    CP16(_d + 32, _sp + 8,  _sz);                                            \
    CP16(_d + 48, _sp + 12, _sz);                                            \
    CP_COMMIT();                                                             \
} while (0)

    G_ISSUE(0);

#pragma unroll 1
    for (int s = 0; s < NSTG; ++s) {
        CP_WAIT(0);
        char* rp = rmyp + (s & 1) * 17408;
        uint16_t* hb = hbuf + (s & 1) * 4096;
#pragma unroll
        for (int i = 0; i < 4; ++i) {
            float4 v = *(const float4*)(rp + 16 * i);
            sx += v.x + v.y + v.z + v.w;
            uint2 hp = cvt_h4(v);
            const int col = sq * 16 + 4 * i;
            const int ad = srow * 128 + ((((col >> 3) ^ (srow & 7))) << 4) + ((col & 7) << 1);
            *(uint2*)((char*)hb + ad) = hp;
        }
        if (s + 1 < NSTG) G_ISSUE(s + 1);
        __syncthreads();

        const uint32_t sbb = hbase + (s & 1) * 8192;
#pragma unroll
        for (int k = 0; k < 4; ++k) {
            const int c0 = k * 2;
            uint32_t a[4], bh[8];
            LDSM4(a, sbb + arow * 128 + (((c0 + achk) ^ (arow & 7)) << 4));
            LDSM4(bh + 0, sbb + brow0 * 128 + (((c0 + bchk) ^ (brow0 & 7)) << 4));
            LDSM4(bh + 4, sbb + brow1 * 128 + (((c0 + bchk) ^ (brow1 & 7)) << 4));
#pragma unroll
            for (int j = 0; j < 4; ++j)
                MMAF16(D[j], a, bh[2 * j], bh[2 * j + 1]);
        }
    }

    red[tid] = sx;
    __syncthreads();
    if (tid < 64)
        g_sxp[(b * TS_ + split) * C_ + tid] =
            red[4 * tid] + red[4 * tid + 1] + red[4 * tid + 2] + red[4 * tid + 3];

    float* gp = g_gp + (size_t)(b * TS_ + split) * (C_ * C_);
    const int crow = 16 * mg + (lane >> 2);
    const int ccol0 = 32 * ng + 2 * (lane & 3);
#pragma unroll
    for (int j = 0; j < 4; ++j) {
        const int c = ccol0 + 8 * j;
        *(float2*)(gp + crow * C_ + c)       = make_float2(D[j][0], D[j][1]);
        *(float2*)(gp + (crow + 8) * C_ + c) = make_float2(D[j][2], D[j][3]);
    }
}

// ---------------------------------------------------------------------------
// Kernel B (R10 proven): reduce partials, min-max + softmax, emit gamma*M^T.
// ---------------------------------------------------------------------------
__global__ void __launch_bounds__(256) k_attn(const float* __restrict__ w1,
                                              const float* __restrict__ b1,
                                              const float* __restrict__ w2,
                                              const float* __restrict__ b2,
                                              const float* __restrict__ gptr) {
    __shared__ float Es[C_][65];
    __shared__ float sxs[C_];
    const int b = blockIdx.x;
    const int tid = threadIdx.x;

    float S11 = 0.f, S21 = 0.f;
#pragma unroll
    for (int j = 0; j < 8; ++j) { S11 += w1[j] * w2[j]; S21 += b1[j] * w2[j]; }
    const float ga = *gptr;

    if (tid < 64) {
        float s = 0.f;
#pragma unroll
        for (int p = 0; p < TS_; ++p) s += g_sxp[(b * TS_ + p) * C_ + tid];
        sxs[tid] = s;
    }
    __syncthreads();

    const float* gp = g_gp + (size_t)b * TS_ * (C_ * C_);
    for (int i = tid; i < C_ * C_; i += 256) {
        float g = 0.f;
#pragma unroll
        for (int p = 0; p < TS_; ++p) g += gp[p * (C_ * C_) + i];
        const int e = i & 63;
        Es[i >> 6][e] = S11 * g + S21 * sxs[e];
    }
    __syncthreads();

    const int wid = tid >> 5, lane = tid & 31;
    char* ath = (char*)g_ath + (size_t)b * 8192;
    for (int r = wid; r < C_; r += 8) {
        float v0 = Es[r][lane], v1 = Es[r][lane + 32];
        float mx = fmaxf(v0, v1), mn = fminf(v0, v1);
#pragma unroll
        for (int o = 16; o; o >>= 1) {
            mx = fmaxf(mx, __shfl_xor_sync(0xffffffffu, mx, o));
            mn = fminf(mn, __shfl_xor_sync(0xffffffffu, mn, o));
        }
        const float inv = 1.f / (mx - mn + 1e-8f);
        const float nmax = (mx - mn) * inv;
        float e0 = expf((v0 - mn) * inv - nmax);
        float e1 = expf((v1 - mn) * inv - nmax);
        float s = e0 + e1;
#pragma unroll
        for (int o = 16; o; o >>= 1) s += __shfl_xor_sync(0xffffffffu, s, o);
        const float invs = ga / s;     // fold gamma into M
        const __half h0 = __float2half_rn(e0 * invs);
        const __half h1 = __float2half_rn(e1 * invs);
        const int c0 = lane, c1 = lane + 32;
        *(uint16_t*)(ath + c0 * 128 + (((r >> 3) ^ (c0 & 7)) << 4) + ((r & 7) << 1)) =
            *(const uint16_t*)&h0;
        *(uint16_t*)(ath + c1 * 128 + (((r >> 3) ^ (c1 & 7)) << 4) + ((r & 7) << 1)) =
            *(const uint16_t*)&h1;
    }
}

// ---------------------------------------------------------------------------
// Kernel C: out = x + (gamma*M)^T X. Quarter-pipelined fp32 staging:
// 2 x 10KB ring of 10KB quarters (16 rows x 160 t). smem 53.2KB -> 4 CTAs/SM.
// Quarter m: wait(1) [m landed, m+1 in flight] -> convert -> issue m+2.
// Buffer m&1 reuse is safe: same thread converts exactly the slots it issues.
// ---------------------------------------------------------------------------
__global__ void __launch_bounds__(256, 4) k_apply_mma(const float* __restrict__ x,
                                                      float* __restrict__ out) {
    uint16_t* At = (uint16_t*)smem_dyn;     // 8 KB fp16 swizzled (gamma*M^T)
    uint16_t* Xs = At + 4096;               // 24 KB fp16 [64][192] swizzled
    float*    Xf = (float*)(Xs + 64 * 192); // 2 x 10 KB fp32 quarter ring

    const int b = blockIdx.y, ckb = blockIdx.x;
    const int tid = threadIdx.x, lane = tid & 31, wid = tid >> 5;
    const int mg = wid >> 1, ngw = wid & 1;

    // stage At once (pre-swizzled + gamma-folded)
    {
        const float4* src = (const float4*)((const char*)g_ath + (size_t)b * 8192);
        float4* dst = (float4*)At;
        dst[tid] = src[tid];
        dst[tid + 256] = src[tid + 256];
    }

    const float* xb = x + (size_t)b * C_ * T_;
    const uint32_t xfb = smem_u32(Xf);

    const int c0 = ckb * CHPC;
    const int ncks = (c0 + CHPC <= NCH_C) ? CHPC : (NCH_C - c0);
    const int NQ = ncks * 4;

    // quarter m: chunk c0 + (m>>2), rows [16*(m&3), +16), buffer m&1
#define Q_ISSUE(m) do {                                                      \
    const int _ck = c0 + ((m) >> 2), _qq = (m) & 3;                          \
    const int _t0 = _ck * TC_C;                                              \
    const uint32_t _xd = xfb + ((m) & 1) * 10240;                            \
    _Pragma("unroll")                                                        \
    for (int _v = tid; _v < 640; _v += 256) {                                \
        const int _row = 16 * _qq + _v / 40, _tq = _v % 40;                  \
        CP16F(_xd + _v * 16, xb + (size_t)_row * T_ + _t0 + 4 * _tq);        \
    }                                                                        \
    CP_COMMIT();                                                             \
} while (0)

    Q_ISSUE(0);
    Q_ISSUE(1);

    const int arow = 16 * mg + (lane & 7) + 8 * ((lane >> 3) & 1);
    const int achk = lane >> 4;
    const int bkoff = 8 * ((lane >> 3) & 1) + (lane & 7);
    const int bjj = lane >> 4;
    const int orow = 16 * mg + (lane >> 2);

#pragma unroll 1
    for (int j = 0; j < ncks; ++j) {
        const int ck = c0 + j;
        const int t0 = ck * TC_C;

#pragma unroll 1
        for (int q = 0; q < 4; ++q) {
            const int m = 4 * j + q;
            if (m == NQ - 1) CP_WAIT(0); else CP_WAIT(1);
            // convert quarter m (rows 16q..16q+16) from buffer m&1
            const float* xf = Xf + (m & 1) * 2560;
#pragma unroll
            for (int v = tid; v < 640; v += 256) {
                const int row = 16 * q + v / 40, tq = v % 40;
                float4 w = *(const float4*)(xf + v * 4);
                uint2 hp = cvt_h4(w);
                const int col = 4 * tq;
                const int ad = row * 384 + ((((col >> 3) ^ (row & 7))) << 4) + ((col & 7) << 1);
                *(uint2*)((char*)Xs + ad) = hp;
            }
            if (m + 2 < NQ) Q_ISSUE(m + 2);
        }
        __syncthreads();                 // all 4 quarters converted

        float acc[10][4];
#pragma unroll
        for (int jj = 0; jj < 10; ++jj)
#pragma unroll
            for (int i = 0; i < 4; ++i) acc[jj][i] = 0.f;

#pragma unroll
        for (int kk = 0; kk < 4; ++kk) {
            uint32_t ah[4];
            LDSM4(ah, smem_u32(At) + arow * 128 + (((kk * 2 + achk) ^ (arow & 7)) << 4));
            const int krow = kk * 16 + bkoff;
#pragma unroll
            for (int p = 0; p < 5; ++p) {
                const int nchunk = ngw * 10 + 2 * p + bjj;
                uint32_t bh[4];
                LDSM4T(bh, smem_u32(Xs) + krow * 384 + ((nchunk ^ (krow & 7)) << 4));
                MMAF16(acc[2 * p],     ah, bh[0], bh[1]);
                MMAF16(acc[2 * p + 1], ah, bh[2], bh[3]);
            }
        }

        // epilogue: out = x_fp16(smem) + acc
        float* ob = out + (size_t)b * C_ * T_ + t0;
#pragma unroll
        for (int jj = 0; jj < 10; ++jj) {
            const int tc = ngw * 80 + 8 * jj + 2 * (lane & 3);
            const int ad0 = orow * 384 + (((tc >> 3) ^ (orow & 7)) << 4) + ((tc & 7) << 1);
            const int ad1 = (orow + 8) * 384 + (((tc >> 3) ^ ((orow + 8) & 7)) << 4) + ((tc & 7) << 1);
            __half2 xh0 = *(const __half2*)((const char*)Xs + ad0);
            __half2 xh1 = *(const __half2*)((const char*)Xs + ad1);
            float2 x0 = __half22float2(xh0);
            float2 x1 = __half22float2(xh1);
            float2 o0 = make_float2(acc[jj][0] + x0.x, acc[jj][1] + x0.y);
            float2 o1 = make_float2(acc[jj][2] + x1.x, acc[jj][3] + x1.y);
            *(float2*)(ob + (size_t)orow * T_ + tc) = o0;
            *(float2*)(ob + (size_t)(orow + 8) * T_ + tc) = o1;
        }
        __syncthreads();                  // Xs reads done before next converts
    }
}

// ---------------------------------------------------------------------------
extern "C" void kernel_launch(void* const* d_in, const int* in_sizes, int n_in,
                              void* d_out, int out_size) {
    const float* x  = (const float*)d_in[0];
    const float* w1 = (const float*)d_in[1];
    const float* b1 = (const float*)d_in[2];
    const float* w2 = (const float*)d_in[3];
    const float* b2 = (const float*)d_in[4];
    const float* gm = (const float*)d_in[5];
    float* out = (float*)d_out;

    const int smem_gram  = 34816 + 2 * 8192;            // 51,200 B -> 4 CTAs/SM
    const int smem_apply = 8192 + 24576 + 2 * 10240;    // 53,248 B -> 4 CTAs/SM
    cudaFuncSetAttribute(k_gram_mma,  cudaFuncAttributeMaxDynamicSharedMemorySize, smem_gram);
    cudaFuncSetAttribute(k_apply_mma, cudaFuncAttributeMaxDynamicSharedMemorySize, smem_apply);

    k_gram_mma<<<dim3(TS_, B_), 256, smem_gram>>>(x);
    k_attn<<<B_, 256>>>(w1, b1, w2, b2, gm);
    k_apply_mma<<<dim3(NCKB, B_), 256, smem_apply>>>(x, out);
}

// round 16
// speedup vs baseline: 1.1922x; 1.1049x over previous
#include <cuda_runtime.h>
#include <cuda_fp16.h>
#include <cstdint>

#define B_ 64
#define C_ 64
#define T_ 4000
#define TS_ 10           // t-splits for gram
#define TSPAN 400        // t per split
#define NSTG 7           // stages of 64 t (6 full + 16-t remainder)
#define TC_C 160         // t-chunk width for apply kernel
#define NCH_C 25
#define CHPC 2           // chunks per apply CTA
#define NCKB 13          // ceil(25/2) apply CTAs along t

// Scratch (static device globals — allocation-free)
__device__ float g_gp[B_ * TS_ * C_ * C_];   // partial Grams (10.5 MB)
__device__ float g_sxp[B_ * TS_ * C_];       // partial channel sums
__device__ uint16_t g_ath[B_ * 4096];        // gamma*M^T, fp16, swizzled (8KB/batch)

extern __shared__ float smem_dyn[];

__device__ __forceinline__ uint32_t smem_u32(const void* p) {
    uint32_t a;
    asm("{ .reg .u64 t; cvta.to.shared.u64 t, %1; cvt.u32.u64 %0, t; }" : "=r"(a) : "l"(p));
    return a;
}

#define LDSM4(r, addr)                                                       \
    asm volatile("ldmatrix.sync.aligned.m8n8.x4.shared.b16 {%0,%1,%2,%3}, [%4];" \
        : "=r"((r)[0]), "=r"((r)[1]), "=r"((r)[2]), "=r"((r)[3]) : "r"(addr))

#define LDSM4T(r, addr)                                                      \
    asm volatile("ldmatrix.sync.aligned.m8n8.x4.trans.shared.b16 {%0,%1,%2,%3}, [%4];" \
        : "=r"((r)[0]), "=r"((r)[1]), "=r"((r)[2]), "=r"((r)[3]) : "r"(addr))

#define MMAF16(c, a, b0v, b1v)                                               \
    asm volatile("mma.sync.aligned.m16n8k16.row.col.f32.f16.f16.f32 "        \
        "{%0,%1,%2,%3}, {%4,%5,%6,%7}, {%8,%9}, {%0,%1,%2,%3};"              \
        : "+f"((c)[0]), "+f"((c)[1]), "+f"((c)[2]), "+f"((c)[3])             \
        : "r"((a)[0]), "r"((a)[1]), "r"((a)[2]), "r"((a)[3]),                \
          "r"(b0v), "r"(b1v))

#define CP16(dst, src, sz)                                                   \
    asm volatile("cp.async.cg.shared.global [%0], [%1], 16, %2;"             \
        :: "r"(dst), "l"(src), "r"(sz) : "memory")
#define CP16F(dst, src)                                                      \
    asm volatile("cp.async.cg.shared.global [%0], [%1], 16;"                 \
        :: "r"(dst), "l"(src) : "memory")
#define CP_COMMIT()  asm volatile("cp.async.commit_group;" ::: "memory")
#define CP_WAIT(n)   asm volatile("cp.async.wait_group %0;" :: "n"(n) : "memory")

__device__ __forceinline__ uint2 cvt_h4(float4 v) {
    __half2 p0 = __floats2half2_rn(v.x, v.y);
    __half2 p1 = __floats2half2_rn(v.z, v.w);
    uint2 r;
    r.x = *(uint32_t*)&p0;
    r.y = *(uint32_t*)&p1;
    return r;
}

// ---------------------------------------------------------------------------
// Kernel A (R9/R10 proven, 27.8us): partial Gram over a 400-t split.
// ---------------------------------------------------------------------------
__global__ void __launch_bounds__(256, 4) k_gram_mma(const float* __restrict__ x) {
    char* ring = (char*)smem_dyn;                 // 2 x [64 rows x 272B] = 34816 B
    uint16_t* hbuf = (uint16_t*)(ring + 34816);   // 2 x 8KB fp16 swizzled
    __shared__ float red[256];

    const int split = blockIdx.x, b = blockIdx.y;
    const int tid = threadIdx.x, lane = tid & 31, wid = tid >> 5;
    const int mg = wid >> 1, ng = wid & 1;
    const uint32_t hbase = smem_u32(hbuf);

    const int srow = tid >> 2, sq = tid & 3;
    const float* xsrc = x + ((size_t)b * C_ + srow) * T_ + split * TSPAN + sq * 16;
    const uint32_t rmy = smem_u32(ring) + srow * 272 + sq * 64;
    char* rmyp = ring + srow * 272 + sq * 64;

    const int arow = 16 * mg + (lane & 7) + 8 * ((lane >> 3) & 1);
    const int achk = lane >> 4;
    const int brow0 = 32 * ng + 8 * (lane >> 4) + (lane & 7);
    const int brow1 = brow0 + 16;
    const int bchk = (lane >> 3) & 1;

    float D[4][4];
#pragma unroll
    for (int j = 0; j < 4; ++j)
#pragma unroll
        for (int i = 0; i < 4; ++i) D[j][i] = 0.f;
    float sx = 0.f;

#define G_ISSUE(s) do {                                                      \
    const uint32_t _d = rmy + ((s) & 1) * 17408;                             \
    const int _sz = ((s) < NSTG - 1 || sq == 0) ? 16 : 0;                    \
    const float* _sp = _sz ? (xsrc + (s) * 64) : xsrc;                       \
    CP16(_d,      _sp,      _sz);                                            \
    CP16(_d + 16, _sp + 4,  _sz);                                            \
    CP16(_d + 32, _sp + 8,  _sz);                                            \
    CP16(_d + 48, _sp + 12, _sz);                                            \
    CP_COMMIT();                                                             \
} while (0)

    G_ISSUE(0);

#pragma unroll 1
    for (int s = 0; s < NSTG; ++s) {
        CP_WAIT(0);
        char* rp = rmyp + (s & 1) * 17408;
        uint16_t* hb = hbuf + (s & 1) * 4096;
#pragma unroll
        for (int i = 0; i < 4; ++i) {
            float4 v = *(const float4*)(rp + 16 * i);
            sx += v.x + v.y + v.z + v.w;
            uint2 hp = cvt_h4(v);
            const int col = sq * 16 + 4 * i;
            const int ad = srow * 128 + ((((col >> 3) ^ (srow & 7))) << 4) + ((col & 7) << 1);
            *(uint2*)((char*)hb + ad) = hp;
        }
        if (s + 1 < NSTG) G_ISSUE(s + 1);
        __syncthreads();

        const uint32_t sbb = hbase + (s & 1) * 8192;
#pragma unroll
        for (int k = 0; k < 4; ++k) {
            const int c0 = k * 2;
            uint32_t a[4], bh[8];
            LDSM4(a, sbb + arow * 128 + (((c0 + achk) ^ (arow & 7)) << 4));
            LDSM4(bh + 0, sbb + brow0 * 128 + (((c0 + bchk) ^ (brow0 & 7)) << 4));
            LDSM4(bh + 4, sbb + brow1 * 128 + (((c0 + bchk) ^ (brow1 & 7)) << 4));
#pragma unroll
            for (int j = 0; j < 4; ++j)
                MMAF16(D[j], a, bh[2 * j], bh[2 * j + 1]);
        }
    }

    red[tid] = sx;
    __syncthreads();
    if (tid < 64)
        g_sxp[(b * TS_ + split) * C_ + tid] =
            red[4 * tid] + red[4 * tid + 1] + red[4 * tid + 2] + red[4 * tid + 3];

    float* gp = g_gp + (size_t)(b * TS_ + split) * (C_ * C_);
    const int crow = 16 * mg + (lane >> 2);
    const int ccol0 = 32 * ng + 2 * (lane & 3);
#pragma unroll
    for (int j = 0; j < 4; ++j) {
        const int c = ccol0 + 8 * j;
        *(float2*)(gp + crow * C_ + c)       = make_float2(D[j][0], D[j][1]);
        *(float2*)(gp + (crow + 8) * C_ + c) = make_float2(D[j][2], D[j][3]);
    }
}

// ---------------------------------------------------------------------------
// Kernel B (parallelized): grid (4, B_). CTA (q,b) reduces rows [16q,16q+16)
// of E, softmaxes them, emits gamma*M^T fp16 swizzled rows.
// ---------------------------------------------------------------------------
__global__ void __launch_bounds__(256) k_attn(const float* __restrict__ w1,
                                              const float* __restrict__ b1,
                                              const float* __restrict__ w2,
                                              const float* __restrict__ b2,
                                              const float* __restrict__ gptr) {
    __shared__ float Es[16][65];
    __shared__ float sxs[C_];
    const int q = blockIdx.x, b = blockIdx.y;
    const int tid = threadIdx.x;

    float S11 = 0.f, S21 = 0.f;
#pragma unroll
    for (int j = 0; j < 8; ++j) { S11 += w1[j] * w2[j]; S21 += b1[j] * w2[j]; }
    const float ga = *gptr;

    if (tid < 64) {
        float s = 0.f;
#pragma unroll
        for (int p = 0; p < TS_; ++p) s += g_sxp[(b * TS_ + p) * C_ + tid];
        sxs[tid] = s;
    }
    __syncthreads();

    const float* gp = g_gp + (size_t)b * TS_ * (C_ * C_) + q * 16 * C_;
    for (int i = tid; i < 16 * C_; i += 256) {
        float g = 0.f;
#pragma unroll
        for (int p = 0; p < TS_; ++p) g += gp[p * (C_ * C_) + i];
        const int e = i & 63;
        Es[i >> 6][e] = S11 * g + S21 * sxs[e];
    }
    __syncthreads();

    const int wid = tid >> 5, lane = tid & 31;
    char* ath = (char*)g_ath + (size_t)b * 8192;
    for (int rl = wid; rl < 16; rl += 8) {
        const int r = q * 16 + rl;
        float v0 = Es[rl][lane], v1 = Es[rl][lane + 32];
        float mx = fmaxf(v0, v1), mn = fminf(v0, v1);
#pragma unroll
        for (int o = 16; o; o >>= 1) {
            mx = fmaxf(mx, __shfl_xor_sync(0xffffffffu, mx, o));
            mn = fminf(mn, __shfl_xor_sync(0xffffffffu, mn, o));
        }
        const float inv = 1.f / (mx - mn + 1e-8f);
        const float nmax = (mx - mn) * inv;
        float e0 = expf((v0 - mn) * inv - nmax);
        float e1 = expf((v1 - mn) * inv - nmax);
        float s = e0 + e1;
#pragma unroll
        for (int o = 16; o; o >>= 1) s += __shfl_xor_sync(0xffffffffu, s, o);
        const float invs = ga / s;     // fold gamma into M
        const __half h0 = __float2half_rn(e0 * invs);
        const __half h1 = __float2half_rn(e1 * invs);
        const int c0 = lane, c1 = lane + 32;
        *(uint16_t*)(ath + c0 * 128 + (((r >> 3) ^ (c0 & 7)) << 4) + ((r & 7) << 1)) =
            *(const uint16_t*)&h0;
        *(uint16_t*)(ath + c1 * 128 + (((r >> 3) ^ (c1 & 7)) << 4) + ((r & 7) << 1)) =
            *(const uint16_t*)&h1;
    }
}

// ---------------------------------------------------------------------------
// Kernel C (R10 proven, 33.5us): out = x + (gamma*M)^T X.
// ---------------------------------------------------------------------------
__global__ void __launch_bounds__(256, 3) k_apply_mma(const float* __restrict__ x,
                                                      float* __restrict__ out) {
    uint16_t* At = (uint16_t*)smem_dyn;     // 8 KB fp16 swizzled (gamma*M^T)
    uint16_t* Xs = At + 4096;               // 24 KB fp16 [64][192] swizzled
    float*    Xf = (float*)(Xs + 64 * 192); // 40 KB fp32 linear stage (2560 f4)

    const int b = blockIdx.y, ckb = blockIdx.x;
    const int tid = threadIdx.x, lane = tid & 31, wid = tid >> 5;
    const int mg = wid >> 1, ngw = wid & 1;

    // stage At once: raw vector copy (pre-swizzled + gamma-folded)
    {
        const float4* src = (const float4*)((const char*)g_ath + (size_t)b * 8192);
        float4* dst = (float4*)At;
        dst[tid] = src[tid];
        dst[tid + 256] = src[tid + 256];
    }

    const float* xb = x + (size_t)b * C_ * T_;
    const uint32_t xfb = smem_u32(Xf);

#define A_ISSUE(ck) do {                                                     \
    const int _t0 = (ck) * TC_C;                                             \
    _Pragma("unroll")                                                        \
    for (int k = 0; k < 10; ++k) {                                           \
        const int v = tid + k * 256;                                         \
        const int row = v / 40, q = v % 40;                                  \
        CP16F(xfb + v * 16, xb + (size_t)row * T_ + _t0 + 4 * q);            \
    }                                                                        \
    CP_COMMIT();                                                             \
} while (0)

    const int c0 = ckb * CHPC;
    if (c0 < NCH_C) A_ISSUE(c0);

    const int arow = 16 * mg + (lane & 7) + 8 * ((lane >> 3) & 1);
    const int achk = lane >> 4;
    const int bkoff = 8 * ((lane >> 3) & 1) + (lane & 7);
    const int bjj = lane >> 4;
    const int orow = 16 * mg + (lane >> 2);

#pragma unroll 1
    for (int j = 0; j < CHPC; ++j) {
        const int ck = c0 + j;
        if (ck >= NCH_C) break;
        const int t0 = ck * TC_C;

        CP_WAIT(0);                       // chunk ck's fp32 data landed
#pragma unroll
        for (int k = 0; k < 10; ++k) {
            const int v = tid + k * 256;
            const int row = v / 40, q = v % 40;
            float4 w = *(const float4*)(Xf + v * 4);
            uint2 hp = cvt_h4(w);
            const int col = 4 * q;
            const int ad = row * 384 + ((((col >> 3) ^ (row & 7))) << 4) + ((col & 7) << 1);
            *(uint2*)((char*)Xs + ad) = hp;
        }
        if (j + 1 < CHPC && ck + 1 < NCH_C) A_ISSUE(ck + 1);
        __syncthreads();

        float acc[10][4];
#pragma unroll
        for (int jj = 0; jj < 10; ++jj)
#pragma unroll
            for (int i = 0; i < 4; ++i) acc[jj][i] = 0.f;

#pragma unroll
        for (int kk = 0; kk < 4; ++kk) {
            uint32_t ah[4];
            LDSM4(ah, smem_u32(At) + arow * 128 + (((kk * 2 + achk) ^ (arow & 7)) << 4));
            const int krow = kk * 16 + bkoff;
#pragma unroll
            for (int p = 0; p < 5; ++p) {
                const int nchunk = ngw * 10 + 2 * p + bjj;
                uint32_t bh[4];
                LDSM4T(bh, smem_u32(Xs) + krow * 384 + ((nchunk ^ (krow & 7)) << 4));
                MMAF16(acc[2 * p],     ah, bh[0], bh[1]);
                MMAF16(acc[2 * p + 1], ah, bh[2], bh[3]);
            }
        }

        // epilogue: out = x_fp16(smem) + acc
        float* ob = out + (size_t)b * C_ * T_ + t0;
#pragma unroll
        for (int jj = 0; jj < 10; ++jj) {
            const int tc = ngw * 80 + 8 * jj + 2 * (lane & 3);
            const int ad0 = orow * 384 + (((tc >> 3) ^ (orow & 7)) << 4) + ((tc & 7) << 1);
            const int ad1 = (orow + 8) * 384 + (((tc >> 3) ^ ((orow + 8) & 7)) << 4) + ((tc & 7) << 1);
            __half2 xh0 = *(const __half2*)((const char*)Xs + ad0);
            __half2 xh1 = *(const __half2*)((const char*)Xs + ad1);
            float2 x0 = __half22float2(xh0);
            float2 x1 = __half22float2(xh1);
            float2 o0 = make_float2(acc[jj][0] + x0.x, acc[jj][1] + x0.y);
            float2 o1 = make_float2(acc[jj][2] + x1.x, acc[jj][3] + x1.y);
            *(float2*)(ob + (size_t)orow * T_ + tc) = o0;
            *(float2*)(ob + (size_t)(orow + 8) * T_ + tc) = o1;
        }
        __syncthreads();                  // Xs reads done before next convert
    }
}

// ---------------------------------------------------------------------------
extern "C" void kernel_launch(void* const* d_in, const int* in_sizes, int n_in,
                              void* d_out, int out_size) {
    const float* x  = (const float*)d_in[0];
    const float* w1 = (const float*)d_in[1];
    const float* b1 = (const float*)d_in[2];
    const float* w2 = (const float*)d_in[3];
    const float* b2 = (const float*)d_in[4];
    const float* gm = (const float*)d_in[5];
    float* out = (float*)d_out;

    const int smem_gram  = 34816 + 2 * 8192;            // 51,200 B -> 4 CTAs/SM
    const int smem_apply = 8192 + 24576 + 40960;        // 73,728 B -> 3 CTAs/SM
    cudaFuncSetAttribute(k_gram_mma,  cudaFuncAttributeMaxDynamicSharedMemorySize, smem_gram);
    cudaFuncSetAttribute(k_apply_mma, cudaFuncAttributeMaxDynamicSharedMemorySize, smem_apply);

    k_gram_mma<<<dim3(TS_, B_), 256, smem_gram>>>(x);
    k_attn<<<dim3(4, B_), 256>>>(w1, b1, w2, b2, gm);
    k_apply_mma<<<dim3(NCKB, B_), 256, smem_apply>>>(x, out);
}